// round 6
// baseline (speedup 1.0000x reference)
#include <cuda_runtime.h>
#include <cstdint>

// x [4,512,128] f32, y [512,128] f32 -> out [4,512,512,3] f32 (cos, L1, L2)
#define R_TOTAL 2048
#define C_TOTAL 512
#define D_DIM   128
#define NDD2    (D_DIM / 2)     // 64 packed-pair steps

#define BM 64                   // x rows per block
#define BN 32                   // y rows per block
#define XTS 65                  // xsT row stride in u64 ([dd2][row=64]+1 pad)
#define YTS 34                  // ysT row stride in u64 ([dd2][row=32]+2 pad, keeps 16B align)
#define SMEM_BYTES ((NDD2 * XTS + NDD2 * YTS) * 8)   // 33280 + 17408 = 50688 B

typedef unsigned long long u64;
struct __align__(16) ull2 { u64 x, y; };

// ---------------- precomputed norms ----------------
__device__ float g_xsq[R_TOTAL];
__device__ float g_xrn[R_TOTAL];
__device__ float g_ysq[C_TOTAL];
__device__ float g_yrn[C_TOTAL];

__global__ void norms_kernel(const float* __restrict__ x,
                             const float* __restrict__ y) {
    int w    = (blockIdx.x * blockDim.x + threadIdx.x) >> 5;
    int lane = threadIdx.x & 31;
    if (w >= R_TOTAL + C_TOTAL) return;
    const float* p = (w < R_TOTAL) ? (x + (size_t)w * D_DIM)
                                   : (y + (size_t)(w - R_TOTAL) * D_DIM);
    float4 v = reinterpret_cast<const float4*>(p)[lane];
    float s = v.x * v.x + v.y * v.y + v.z * v.z + v.w * v.w;
    #pragma unroll
    for (int o = 16; o > 0; o >>= 1) s += __shfl_xor_sync(0xFFFFFFFFu, s, o);
    if (lane == 0) {
        float r = rsqrtf(s);
        if (w < R_TOTAL) { g_xsq[w] = s; g_xrn[w] = r; }
        else             { g_ysq[w - R_TOTAL] = s; g_yrn[w - R_TOTAL] = r; }
    }
}

// ---------------- packed f32x2 helpers ----------------
__device__ __forceinline__ u64 ffma2(u64 a, u64 b, u64 c) {
    u64 d;
    asm("fma.rn.f32x2 %0, %1, %2, %3;" : "=l"(d) : "l"(a), "l"(b), "l"(c));
    return d;
}
__device__ __forceinline__ u64 fadd2(u64 a, u64 b) {
    u64 d;
    asm("add.rn.f32x2 %0, %1, %2;" : "=l"(d) : "l"(a), "l"(b));
    return d;
}
__device__ __forceinline__ float f2lo(u64 d) { return __uint_as_float((unsigned)(d & 0xFFFFFFFFu)); }
__device__ __forceinline__ float f2hi(u64 d) { return __uint_as_float((unsigned)(d >> 32)); }
__device__ __forceinline__ u64 pack2(float lo, float hi) {
    return ((u64)__float_as_uint(hi) << 32) | (u64)__float_as_uint(lo);
}

// ---------------- main distance kernel ----------------
// 256 threads: tx = t&15 -> cols {2tx, 2tx+1}; ty = t>>4 -> rows ty+16i (i<4)
// 4 CTAs/SM: 64 regs * 256 thr * 4 = full RF; smem 50688+1K guard * 4 <= 228KB.
__global__ void __launch_bounds__(256, 4)
dist_kernel(const float* __restrict__ x, const float* __restrict__ y,
            float* __restrict__ out) {
    extern __shared__ __align__(16) u64 sm64[];
    u64* xsT = sm64;                    // [NDD2][XTS]
    u64* ysT = sm64 + NDD2 * XTS;       // [NDD2][YTS]

    const int R0 = blockIdx.x * BM;     // grid.x = 32
    const int C0 = blockIdx.y * BN;     // grid.y = 16
    const int t  = threadIdx.x;
    const int tx = t & 15;
    const int ty = t >> 4;

    // ---- stage x tile (64 rows x 128) transposed-packed: 8 float4 per thread
    #pragma unroll
    for (int s = 0; s < 8; s++) {
        int idx  = t + 256 * s;         // 0..2047
        int row  = idx >> 5;            // 0..63
        int col4 = idx & 31;
        float4 v = *reinterpret_cast<const float4*>(
            x + (size_t)(R0 + row) * D_DIM + col4 * 4);
        xsT[(2 * col4) * XTS + row]     = pack2(v.x, v.y);
        xsT[(2 * col4 + 1) * XTS + row] = pack2(v.z, v.w);
    }
    // ---- stage y tile (32 rows x 128): 4 float4 per thread
    #pragma unroll
    for (int s = 0; s < 4; s++) {
        int idx  = t + 256 * s;         // 0..1023
        int row  = idx >> 5;            // 0..31
        int col4 = idx & 31;
        float4 v = *reinterpret_cast<const float4*>(
            y + (size_t)(C0 + row) * D_DIM + col4 * 4);
        ysT[(2 * col4) * YTS + row]     = pack2(v.x, v.y);
        ysT[(2 * col4 + 1) * YTS + row] = pack2(v.z, v.w);
    }
    __syncthreads();

    const u64 NEG1 = 0xBF800000BF800000ULL;   // (-1.f, -1.f)
    const u64 ABSM = 0x7FFFFFFF7FFFFFFFULL;   // packed abs mask

    u64 acc1[4][2];   // packed L1 sums   (rows i, cols j)
    u64 acc2[4][2];   // packed sum of squares
    #pragma unroll
    for (int i = 0; i < 4; i++)
        #pragma unroll
        for (int j = 0; j < 2; j++) { acc1[i][j] = 0ULL; acc2[i][j] = 0ULL; }

    const u64*  px = xsT + ty;                                    // rows ty+16i
    const ull2* py = reinterpret_cast<const ull2*>(ysT + 2 * tx); // cols 2tx,2tx+1

    #pragma unroll 8
    for (int dd2 = 0; dd2 < NDD2; dd2++) {
        u64 xv[4];
        #pragma unroll
        for (int i = 0; i < 4; i++) xv[i] = px[16 * i];           // LDS.64 broadcast
        ull2 yv = *py;                                            // LDS.128 contiguous

        #pragma unroll
        for (int i = 0; i < 4; i++) {
            u64 d0 = ffma2(yv.x, NEG1, xv[i]);   // x - y (2 D-lanes), col 2tx
            u64 d1 = ffma2(yv.y, NEG1, xv[i]);   // col 2tx+1
            acc2[i][0] = ffma2(d0, d0, acc2[i][0]);
            acc2[i][1] = ffma2(d1, d1, acc2[i][1]);
            acc1[i][0] = fadd2(acc1[i][0], d0 & ABSM);
            acc1[i][1] = fadd2(acc1[i][1], d1 & ABSM);
        }

        px += XTS;
        py += YTS / 2;
    }

    // ---- epilogue: cos / p1 / p2 ----
    #pragma unroll
    for (int i = 0; i < 4; i++) {
        int gr = R0 + ty + 16 * i;
        float xsq = g_xsq[gr];
        float xrn = g_xrn[gr];
        #pragma unroll
        for (int j = 0; j < 2; j++) {
            int gc = C0 + 2 * tx + j;
            float s2 = f2lo(acc2[i][j]) + f2hi(acc2[i][j]);
            float s1 = f2lo(acc1[i][j]) + f2hi(acc1[i][j]);
            float p2 = sqrtf(fmaxf(s2, 0.0f));
            float dot = 0.5f * (xsq + g_ysq[gc] - s2);
            float cosv = dot * xrn * g_yrn[gc];
            size_t idx = ((size_t)gr * C_TOTAL + gc) * 3;
            out[idx + 0] = cosv;
            out[idx + 1] = s1;
            out[idx + 2] = p2;
        }
    }
}

extern "C" void kernel_launch(void* const* d_in, const int* in_sizes, int n_in,
                              void* d_out, int out_size) {
    const float* x = (const float*)d_in[0];
    const float* y = (const float*)d_in[1];
    float* out = (float*)d_out;

    cudaFuncSetAttribute(dist_kernel,
                         cudaFuncAttributeMaxDynamicSharedMemorySize, SMEM_BYTES);

    norms_kernel<<<(2560 * 32 + 255) / 256, 256>>>(x, y);

    dim3 grid(R_TOTAL / BM, C_TOTAL / BN);   // 32 x 16 = 512 blocks, 1 wave @ 4 CTA/SM
    dist_kernel<<<grid, 256, SMEM_BYTES>>>(x, y, out);
}

// round 7
// speedup vs baseline: 1.0146x; 1.0146x over previous
#include <cuda_runtime.h>
#include <cstdint>

// x [4,512,128] f32, y [512,128] f32 -> out [4,512,512,3] f32 (cos, L1, L2)
#define R_TOTAL 2048
#define C_TOTAL 512
#define D_DIM   128
#define NDD2    (D_DIM / 2)     // 64 packed-pair steps

#define BM 64                   // x rows per block
#define BN 32                   // y rows per block
#define XTS 65                  // xsT row stride in u64 ([dd2][row=64]+1 pad)
#define YTS 34                  // ysT row stride in u64 ([dd2][row=32]+2 pad, keeps 16B align)
#define NORM_OFF (NDD2 * XTS + NDD2 * YTS)            // u64 offset of norm area
#define SMEM_BYTES (NORM_OFF * 8 + 96 * 2 * 4)        // tiles + 96 (sq,rn) float pairs

typedef unsigned long long u64;
struct __align__(16) ull2 { u64 x, y; };

// ---------------- packed f32x2 helpers ----------------
__device__ __forceinline__ u64 ffma2(u64 a, u64 b, u64 c) {
    u64 d;
    asm("fma.rn.f32x2 %0, %1, %2, %3;" : "=l"(d) : "l"(a), "l"(b), "l"(c));
    return d;
}
__device__ __forceinline__ u64 fadd2(u64 a, u64 b) {
    u64 d;
    asm("add.rn.f32x2 %0, %1, %2;" : "=l"(d) : "l"(a), "l"(b));
    return d;
}
__device__ __forceinline__ float f2lo(u64 d) { return __uint_as_float((unsigned)(d & 0xFFFFFFFFu)); }
__device__ __forceinline__ float f2hi(u64 d) { return __uint_as_float((unsigned)(d >> 32)); }
__device__ __forceinline__ u64 pack2(float lo, float hi) {
    return ((u64)__float_as_uint(hi) << 32) | (u64)__float_as_uint(lo);
}

// ---------------- fused distance kernel ----------------
// 256 threads: tx = t&15 -> cols {2tx, 2tx+1}; ty = t>>4 -> rows ty+16i (i<4)
__global__ void __launch_bounds__(256, 3)
dist_kernel(const float* __restrict__ x, const float* __restrict__ y,
            float* __restrict__ out) {
    extern __shared__ __align__(16) u64 sm64[];
    u64* xsT = sm64;                    // [NDD2][XTS]
    u64* ysT = sm64 + NDD2 * XTS;       // [NDD2][YTS]
    float* nsq = reinterpret_cast<float*>(sm64 + NORM_OFF);  // [96] |row|^2 (64 x, 32 y)
    float* nrn = nsq + 96;                                   // [96] rsqrt

    const int R0 = blockIdx.x * BM;     // grid.x = 32
    const int C0 = blockIdx.y * BN;     // grid.y = 16
    const int t  = threadIdx.x;
    const int tx = t & 15;
    const int ty = t >> 4;

    // ---- stage x tile (64 rows x 128) transposed-packed: 8 float4 per thread
    #pragma unroll
    for (int s = 0; s < 8; s++) {
        int idx  = t + 256 * s;         // 0..2047
        int row  = idx >> 5;            // 0..63
        int col4 = idx & 31;
        float4 v = *reinterpret_cast<const float4*>(
            x + (size_t)(R0 + row) * D_DIM + col4 * 4);
        xsT[(2 * col4) * XTS + row]     = pack2(v.x, v.y);
        xsT[(2 * col4 + 1) * XTS + row] = pack2(v.z, v.w);
    }
    // ---- stage y tile (32 rows x 128): 4 float4 per thread
    #pragma unroll
    for (int s = 0; s < 4; s++) {
        int idx  = t + 256 * s;         // 0..1023
        int row  = idx >> 5;            // 0..31
        int col4 = idx & 31;
        float4 v = *reinterpret_cast<const float4*>(
            y + (size_t)(C0 + row) * D_DIM + col4 * 4);
        ysT[(2 * col4) * YTS + row]     = pack2(v.x, v.y);
        ysT[(2 * col4 + 1) * YTS + row] = pack2(v.z, v.w);
    }
    __syncthreads();

    // ---- fused norms: thread r<64 -> x row r; 64<=r<96 -> y row r-64
    if (t < 96) {
        const u64* base; int stride;
        if (t < 64) { base = xsT + t;        stride = XTS; }
        else        { base = ysT + (t - 64); stride = YTS; }
        u64 a = 0ULL;
        #pragma unroll 8
        for (int dd2 = 0; dd2 < NDD2; dd2++) {
            u64 v = base[dd2 * stride];
            a = ffma2(v, v, a);
        }
        float s = f2lo(a) + f2hi(a);
        nsq[t] = s;
        nrn[t] = rsqrtf(s);
    }
    __syncthreads();

    const u64 NEG1 = 0xBF800000BF800000ULL;   // (-1.f, -1.f)
    const u64 ABSM = 0x7FFFFFFF7FFFFFFFULL;   // packed abs mask

    u64 acc1[4][2];   // packed L1 sums   (rows i, cols j)
    u64 acc2[4][2];   // packed sum of squares
    #pragma unroll
    for (int i = 0; i < 4; i++)
        #pragma unroll
        for (int j = 0; j < 2; j++) { acc1[i][j] = 0ULL; acc2[i][j] = 0ULL; }

    const u64*  px = xsT + ty;                                    // rows ty+16i
    const ull2* py = reinterpret_cast<const ull2*>(ysT + 2 * tx); // cols 2tx,2tx+1

    // ---- software-pipelined mainloop: loads for dd2+1 issued before compute of dd2
    u64  xv[4];
    ull2 yv;
    #pragma unroll
    for (int i = 0; i < 4; i++) xv[i] = px[16 * i];
    yv = *py;

    #pragma unroll 4
    for (int dd2 = 0; dd2 < NDD2 - 1; dd2++) {
        px += XTS;
        py += YTS / 2;
        u64  nxv[4];
        ull2 nyv;
        #pragma unroll
        for (int i = 0; i < 4; i++) nxv[i] = px[16 * i];          // LDS.64 broadcast
        nyv = *py;                                                // LDS.128 contiguous

        #pragma unroll
        for (int i = 0; i < 4; i++) {
            u64 d0 = ffma2(yv.x, NEG1, xv[i]);   // x - y (2 D-lanes), col 2tx
            u64 d1 = ffma2(yv.y, NEG1, xv[i]);   // col 2tx+1
            acc2[i][0] = ffma2(d0, d0, acc2[i][0]);
            acc2[i][1] = ffma2(d1, d1, acc2[i][1]);
            acc1[i][0] = fadd2(acc1[i][0], d0 & ABSM);
            acc1[i][1] = fadd2(acc1[i][1], d1 & ABSM);
        }

        #pragma unroll
        for (int i = 0; i < 4; i++) xv[i] = nxv[i];
        yv = nyv;
    }
    // last iteration
    #pragma unroll
    for (int i = 0; i < 4; i++) {
        u64 d0 = ffma2(yv.x, NEG1, xv[i]);
        u64 d1 = ffma2(yv.y, NEG1, xv[i]);
        acc2[i][0] = ffma2(d0, d0, acc2[i][0]);
        acc2[i][1] = ffma2(d1, d1, acc2[i][1]);
        acc1[i][0] = fadd2(acc1[i][0], d0 & ABSM);
        acc1[i][1] = fadd2(acc1[i][1], d1 & ABSM);
    }

    // ---- epilogue: cos / p1 / p2 ----
    #pragma unroll
    for (int i = 0; i < 4; i++) {
        int lrow = ty + 16 * i;
        int gr = R0 + lrow;
        float xsq = nsq[lrow];
        float xrn = nrn[lrow];
        #pragma unroll
        for (int j = 0; j < 2; j++) {
            int lcol = 2 * tx + j;
            int gc = C0 + lcol;
            float s2 = f2lo(acc2[i][j]) + f2hi(acc2[i][j]);
            float s1 = f2lo(acc1[i][j]) + f2hi(acc1[i][j]);
            float p2 = sqrtf(fmaxf(s2, 0.0f));
            float dot = 0.5f * (xsq + nsq[64 + lcol] - s2);
            float cosv = dot * xrn * nrn[64 + lcol];
            size_t idx = ((size_t)gr * C_TOTAL + gc) * 3;
            out[idx + 0] = cosv;
            out[idx + 1] = s1;
            out[idx + 2] = p2;
        }
    }
}

extern "C" void kernel_launch(void* const* d_in, const int* in_sizes, int n_in,
                              void* d_out, int out_size) {
    const float* x = (const float*)d_in[0];
    const float* y = (const float*)d_in[1];
    float* out = (float*)d_out;

    cudaFuncSetAttribute(dist_kernel,
                         cudaFuncAttributeMaxDynamicSharedMemorySize, SMEM_BYTES);

    dim3 grid(R_TOTAL / BM, C_TOTAL / BN);   // 32 x 16 = 512 blocks
    dist_kernel<<<grid, 256, SMEM_BYTES>>>(x, y, out);
}

// round 8
// speedup vs baseline: 1.0691x; 1.0537x over previous
#include <cuda_runtime.h>
#include <cstdint>

// x [4,512,128] f32, y [512,128] f32 -> out [4,512,512,3] f32 (cos, L1, L2)
#define R_TOTAL 2048
#define C_TOTAL 512
#define D_DIM   128
#define NDD2    (D_DIM / 2)     // 64 packed-pair (2 D-values) steps

#define BM 64                   // x rows per block
#define BN 64                   // y rows per block
#define XTS 65                  // xsT row stride in u64  ([dd2][xrow 0..63] + 1 pad)
#define YTS 66                  // ysT row stride in u64  ([dd2][yrow 0..63] + 2 pad, 16B-aligned)
#define NORM_OFF (NDD2 * XTS + NDD2 * YTS)         // u64 offset of norm area
#define SMEM_BYTES (NORM_OFF * 8 + 128 * 2 * 4)    // tiles + 128 (sq,rn) float pairs

typedef unsigned long long u64;
struct __align__(16) ull2 { u64 x, y; };

// ---------------- packed f32x2 helpers ----------------
__device__ __forceinline__ u64 ffma2(u64 a, u64 b, u64 c) {
    u64 d;
    asm("fma.rn.f32x2 %0, %1, %2, %3;" : "=l"(d) : "l"(a), "l"(b), "l"(c));
    return d;
}
__device__ __forceinline__ u64 fadd2(u64 a, u64 b) {
    u64 d;
    asm("add.rn.f32x2 %0, %1, %2;" : "=l"(d) : "l"(a), "l"(b));
    return d;
}
__device__ __forceinline__ float f2lo(u64 d) { return __uint_as_float((unsigned)(d & 0xFFFFFFFFu)); }
__device__ __forceinline__ float f2hi(u64 d) { return __uint_as_float((unsigned)(d >> 32)); }
__device__ __forceinline__ u64 pack2(float lo, float hi) {
    return ((u64)__float_as_uint(hi) << 32) | (u64)__float_as_uint(lo);
}

// ---------------- fused distance kernel ----------------
// 256 threads: tx = t&15 -> y rows {4tx..4tx+3}; ty = t>>4 -> x rows ty+16i (i<4)
__global__ void __launch_bounds__(256, 2)
dist_kernel(const float* __restrict__ x, const float* __restrict__ y,
            float* __restrict__ out) {
    extern __shared__ __align__(16) u64 sm64[];
    u64* xsT = sm64;                    // [NDD2][XTS]
    u64* ysT = sm64 + NDD2 * XTS;       // [NDD2][YTS]
    float* nsq = reinterpret_cast<float*>(sm64 + NORM_OFF);  // [128]: 64 x + 64 y
    float* nrn = nsq + 128;

    const int R0 = blockIdx.x * BM;     // grid.x = 32
    const int C0 = blockIdx.y * BN;     // grid.y = 8
    const int t  = threadIdx.x;
    const int tx = t & 15;
    const int ty = t >> 4;

    // ---- stage x tile (64 rows x 128) transposed-packed: 8 float4 per thread
    #pragma unroll
    for (int s = 0; s < 8; s++) {
        int idx  = t + 256 * s;         // 0..2047
        int row  = idx >> 5;            // 0..63
        int col4 = idx & 31;
        float4 v = *reinterpret_cast<const float4*>(
            x + (size_t)(R0 + row) * D_DIM + col4 * 4);
        xsT[(2 * col4) * XTS + row]     = pack2(v.x, v.y);
        xsT[(2 * col4 + 1) * XTS + row] = pack2(v.z, v.w);
    }
    // ---- stage y tile (64 rows x 128): 8 float4 per thread
    #pragma unroll
    for (int s = 0; s < 8; s++) {
        int idx  = t + 256 * s;         // 0..2047
        int row  = idx >> 5;            // 0..63
        int col4 = idx & 31;
        float4 v = *reinterpret_cast<const float4*>(
            y + (size_t)(C0 + row) * D_DIM + col4 * 4);
        ysT[(2 * col4) * YTS + row]     = pack2(v.x, v.y);
        ysT[(2 * col4 + 1) * YTS + row] = pack2(v.z, v.w);
    }
    __syncthreads();

    // ---- fused norms: thread r<64 -> x row r; 64<=r<128 -> y row r-64
    if (t < 128) {
        const u64* base; int stride;
        if (t < 64) { base = xsT + t;        stride = XTS; }
        else        { base = ysT + (t - 64); stride = YTS; }
        u64 a = 0ULL;
        #pragma unroll 8
        for (int dd2 = 0; dd2 < NDD2; dd2++) {
            u64 v = base[dd2 * stride];
            a = ffma2(v, v, a);
        }
        float s = f2lo(a) + f2hi(a);
        nsq[t] = s;
        nrn[t] = rsqrtf(s);
    }
    __syncthreads();

    const u64 NEG1 = 0xBF800000BF800000ULL;   // (-1.f, -1.f)
    const u64 ABSM = 0x7FFFFFFF7FFFFFFFULL;   // packed abs mask

    u64 acc1[4][4];   // packed L1 sums   [x-row i][y-col j]
    u64 acc2[4][4];   // packed sum of squares
    #pragma unroll
    for (int i = 0; i < 4; i++)
        #pragma unroll
        for (int j = 0; j < 4; j++) { acc1[i][j] = 0ULL; acc2[i][j] = 0ULL; }

    const u64*  px = xsT + ty;                                    // x rows ty+16i
    const ull2* py = reinterpret_cast<const ull2*>(ysT + 4 * tx); // y rows 4tx..4tx+3

    #pragma unroll 4
    for (int dd2 = 0; dd2 < NDD2; dd2++) {
        u64 xv[4];
        #pragma unroll
        for (int i = 0; i < 4; i++) xv[i] = px[16 * i];   // LDS.64 broadcast
        ull2 ya = py[0];                                  // y rows 4tx, 4tx+1
        ull2 yb = py[1];                                  // y rows 4tx+2, 4tx+3
        u64 yv[4] = { ya.x, ya.y, yb.x, yb.y };

        #pragma unroll
        for (int i = 0; i < 4; i++) {
            #pragma unroll
            for (int j = 0; j < 4; j++) {
                u64 d = ffma2(yv[j], NEG1, xv[i]);        // x - y (2 D-lanes)
                acc2[i][j] = ffma2(d, d, acc2[i][j]);
                acc1[i][j] = fadd2(acc1[i][j], d & ABSM);
            }
        }

        px += XTS;
        py += YTS / 2;
    }

    // ---- epilogue: cos / p1 / p2, 3x STG.128 per x-row ----
    #pragma unroll
    for (int i = 0; i < 4; i++) {
        int lrow = ty + 16 * i;
        int gr = R0 + lrow;
        float xsq = nsq[lrow];
        float xrn = nrn[lrow];
        float o[12];
        #pragma unroll
        for (int j = 0; j < 4; j++) {
            int lcol = 4 * tx + j;
            float s2 = f2lo(acc2[i][j]) + f2hi(acc2[i][j]);
            float s1 = f2lo(acc1[i][j]) + f2hi(acc1[i][j]);
            float p2 = sqrtf(fmaxf(s2, 0.0f));
            float dot = 0.5f * (xsq + nsq[64 + lcol] - s2);
            float cosv = dot * xrn * nrn[64 + lcol];
            o[3 * j + 0] = cosv;
            o[3 * j + 1] = s1;
            o[3 * j + 2] = p2;
        }
        // base = (gr*512 + C0 + 4tx)*3 ; 12 consecutive floats, 16B-aligned
        size_t base = ((size_t)gr * C_TOTAL + C0 + 4 * tx) * 3;
        float4* dst = reinterpret_cast<float4*>(out + base);
        dst[0] = make_float4(o[0], o[1], o[2],  o[3]);
        dst[1] = make_float4(o[4], o[5], o[6],  o[7]);
        dst[2] = make_float4(o[8], o[9], o[10], o[11]);
    }
}

extern "C" void kernel_launch(void* const* d_in, const int* in_sizes, int n_in,
                              void* d_out, int out_size) {
    const float* x = (const float*)d_in[0];
    const float* y = (const float*)d_in[1];
    float* out = (float*)d_out;

    cudaFuncSetAttribute(dist_kernel,
                         cudaFuncAttributeMaxDynamicSharedMemorySize, SMEM_BYTES);

    dim3 grid(R_TOTAL / BM, C_TOTAL / BN);   // 32 x 8 = 256 blocks, 2 CTA/SM
    dist_kernel<<<grid, 256, SMEM_BYTES>>>(x, y, out);
}